// round 14
// baseline (speedup 1.0000x reference)
#include <cuda_runtime.h>
#include <math.h>
#include <stdint.h>

// Problem constants
#define BB 4
#define NN 8192
#define KK 16
#define BNK (BB * NN * KK)   // 524288

#define W_GRID_BLOCKS (16 * 32 * 4)  // w_pass grid (x*y*z) = 2048
// ring 5 slots * 4 rows * 512 floats (2KB/row) = 40KB; shS 16KB; rn/rd 2KB
#define SLOT_FLOATS (4 * 512)                  // 2048 floats = 8KB per slot
#define DYN_SMEM (5*SLOT_FLOATS*4 + 256*16*4 + 2*256*4)   // 40960+16384+2048

// ---------------------------------------------------------------------------
// Device scratch (no allocations allowed)
// ---------------------------------------------------------------------------
__device__ float    g_S[BNK];            // softmax(logits)
__device__ double   g_StS[BB * KK * KK]; // per-batch S^T S (1024 doubles)
__device__ double   g_num;               // sum W[n,m] * dot(S_n, S_m)
__device__ double   g_den;               // sum W
__device__ unsigned g_done;              // finished-block counter

// ---------------------------------------------------------------------------
// Packed f32x2 helpers
// ---------------------------------------------------------------------------
typedef unsigned long long u64p; // carrier for packed 2 x fp32

__device__ __forceinline__ u64p pk2(float lo, float hi) {
    u64p d;
    asm("mov.b64 %0, {%1, %2};" : "=l"(d) : "f"(lo), "f"(hi));
    return d;
}
__device__ __forceinline__ u64p mul2(u64p a, u64p b) {
    u64p d;
    asm("mul.rn.f32x2 %0, %1, %2;" : "=l"(d) : "l"(a), "l"(b));
    return d;
}
__device__ __forceinline__ u64p fma2(u64p a, u64p b, u64p c) {
    u64p d;
    asm("fma.rn.f32x2 %0, %1, %2, %3;" : "=l"(d) : "l"(a), "l"(b), "l"(c));
    return d;
}
__device__ __forceinline__ float hsum2(u64p d) {
    float lo, hi;
    asm("mov.b64 {%0, %1}, %2;" : "=f"(lo), "=f"(hi) : "l"(d));
    return lo + hi;
}

// ---------------------------------------------------------------------------
// cp.async helper: 16B L1-bypass (.cg) — the R13 lesson: 8B .ca doubled L1
// work and made L1 the wall; copies must stay 16B .cg.
// ---------------------------------------------------------------------------
__device__ __forceinline__ void cp_async16(uint32_t smem_addr, const void* gptr) {
    asm volatile("cp.async.cg.shared.global [%0], [%1], 16;"
                 :: "r"(smem_addr), "l"(gptr) : "memory");
}
#define CP_COMMIT() asm volatile("cp.async.commit_group;" ::: "memory")
#define CP_WAIT3()  asm volatile("cp.async.wait_group 3;" ::: "memory")

// ---------------------------------------------------------------------------
// Softmax over K=16 per row. One thread per row. Block 0 zeroes ALL
// accumulators (strided — 1024 StS entries > 256 threads).
// ---------------------------------------------------------------------------
__global__ void softmax_kernel(const float* __restrict__ logits,
                               float* __restrict__ outS) {
    if (blockIdx.x == 0) {
        int t = threadIdx.x;
        for (int i = t; i < BB * KK * KK; i += 256) g_StS[i] = 0.0;
        if (t == 0) { g_num = 0.0; g_den = 0.0; }
    }
    int row = blockIdx.x * blockDim.x + threadIdx.x; // 0 .. B*N-1
    const float4* lp = (const float4*)(logits + (size_t)row * KK);
    float4 v0 = lp[0], v1 = lp[1], v2 = lp[2], v3 = lp[3];
    float v[16] = { v0.x, v0.y, v0.z, v0.w, v1.x, v1.y, v1.z, v1.w,
                    v2.x, v2.y, v2.z, v2.w, v3.x, v3.y, v3.z, v3.w };
    float mx = v[0];
#pragma unroll
    for (int i = 1; i < 16; i++) mx = fmaxf(mx, v[i]);
    float s = 0.f;
#pragma unroll
    for (int i = 0; i < 16; i++) { v[i] = expf(v[i] - mx); s += v[i]; }
    float inv = 1.0f / s;
    float4 o0 = make_float4(v[0]*inv,  v[1]*inv,  v[2]*inv,  v[3]*inv);
    float4 o1 = make_float4(v[4]*inv,  v[5]*inv,  v[6]*inv,  v[7]*inv);
    float4 o2 = make_float4(v[8]*inv,  v[9]*inv,  v[10]*inv, v[11]*inv);
    float4 o3 = make_float4(v[12]*inv, v[13]*inv, v[14]*inv, v[15]*inv);
    float4* sp = (float4*)(g_S + (size_t)row * KK);
    sp[0] = o0; sp[1] = o1; sp[2] = o2; sp[3] = o3;
    if (outS) {
        float4* op = (float4*)(outS + (size_t)row * KK);
        op[0] = o0; op[1] = o1; op[2] = o2; op[3] = o3;
    }
}

// ---------------------------------------------------------------------------
// Fused main pass:
//   num += W[b,n,m] * dot16(S_n, S_m);  den += W[b,n,m]
//   + StS partials (blockIdx.x==0 blocks) + finalize (last block).
//
// 256 threads = 8 warps, 3 CTAs/SM (24 warps). Each thread owns 2 columns m
// (32-reg sm). Block covers 512 columns x 256 rows. W streams via a
// BLOCK-COOPERATIVE cp.async.cg ring (16B per copy, fully coalesced,
// L1-bypass): 5 slots, prefetch distance 3, ONE __syncthreads per 4-row
// chunk. Barrier in iter k (after wait_group 3, before compute) guarantees
// chunk-k visibility across threads AND that chunk k-1 is consumed, so
// issuing chunk k+3 into slot (k+3)%5 (last consumed at k-2) never races.
// ---------------------------------------------------------------------------
__global__ void __launch_bounds__(256, 3)
w_pass_kernel(const float* __restrict__ W, float* __restrict__ out,
              int loss_idx) {
    extern __shared__ char dyn[];
    float* shWf = (float*)dyn;                           // 5*2048 floats, 40KB
    float* shS  = (float*)(dyn + 5 * SLOT_FLOATS * 4);   // 256x16, 16KB
    float* rn   = shS + 256 * 16;                        // 1KB
    float* rd   = rn + 256;                              // 1KB

    const int tid  = threadIdx.x;
    const int lane = tid & 31;
    const int warp = tid >> 5;
    const int b  = blockIdx.z;
    const int c0 = blockIdx.x * 512 + warp * 64 + lane * 2; // 2 columns m
    const int r0 = blockIdx.y * 256;                         // 256 rows

    // Cooperative copy task: 512 x 16B per 4-row chunk; thread does 2.
    const int tcol  = tid & 127;          // 16B segment within a row
    const int trow  = tid >> 7;           // 0 or 1 (rows 0-1); +2 for second
    const uint32_t swbase = (uint32_t)__cvta_generic_to_shared(shWf);
    const uint32_t soff1 = (uint32_t)(trow * 512 + tcol * 4) * 4;      // bytes
    const uint32_t soff2 = soff1 + 2 * 512 * 4;
    const uint32_t slotB = SLOT_FLOATS * 4;                            // 8KB

    // Stage 256 S_n rows (16KB) once
    {
        const float4* src = (const float4*)(g_S + ((size_t)b * NN + r0) * KK);
        float4* dst = (float4*)shS;
        dst[tid]       = src[tid];
        dst[tid + 256] = src[tid + 256];
        dst[tid + 512] = src[tid + 512];
        dst[tid + 768] = src[tid + 768];
    }

    // Pre-pack S_m for this thread's 2 columns: 2 x 8 packed pairs (32 regs)
    u64p sm[2][8];
#pragma unroll
    for (int jj = 0; jj < 2; jj++) {
        const float4* sp = (const float4*)(g_S + ((size_t)b * NN + (c0 + jj)) * KK);
        float4 a = __ldg(sp), b4 = __ldg(sp + 1), c = __ldg(sp + 2), d = __ldg(sp + 3);
        sm[jj][0] = pk2(a.x, a.y);   sm[jj][1] = pk2(a.z, a.w);
        sm[jj][2] = pk2(b4.x, b4.y); sm[jj][3] = pk2(b4.z, b4.w);
        sm[jj][4] = pk2(c.x, c.y);   sm[jj][5] = pk2(c.z, c.w);
        sm[jj][6] = pk2(d.x, d.y);   sm[jj][7] = pk2(d.z, d.w);
    }

    // Block-base W pointer for the cooperative copies (row r0, col strip)
    const float* Wblk = W + ((size_t)b * NN + r0) * NN + blockIdx.x * 512;
    const size_t g1 = (size_t)trow * NN + (size_t)tcol * 4;
    const size_t g2 = g1 + 2 * (size_t)NN;

    __syncthreads();   // shS resident (also covers first ring writes ordering)

    // Prologue: chunks 0,1,2 into slots 0,1,2
#pragma unroll
    for (int k = 0; k < 3; k++) {
        const float* p = Wblk + (size_t)k * 4 * NN;
        const uint32_t sb = swbase + (uint32_t)k * slotB;
        cp_async16(sb + soff1, p + g1);
        cp_async16(sb + soff2, p + g2);
        CP_COMMIT();
    }

    u64p acc0 = 0, acc1 = 0;      // packed num accumulators (one per column)
    float den0 = 0.f, den1 = 0.f;

    const float2* wcons0 = (const float2*)(shWf + warp * 64) + lane; // row 0 base
    int slot = 0;     // k % 5
    int islot = 3;    // (k+3) % 5

#pragma unroll 1
    for (int k = 0; k < 64; k++) {               // 64 chunks x 4 rows
        if (k + 3 < 64) {
            const float* p = Wblk + (size_t)(k + 3) * 4 * NN;
            const uint32_t sb = swbase + (uint32_t)islot * slotB;
            cp_async16(sb + soff1, p + g1);
            cp_async16(sb + soff2, p + g2);
        }
        CP_COMMIT();   // empty commits on the tail keep group count exact
        CP_WAIT3();    // own copies of chunk k drained
        __syncthreads(); // everyone's chunk-k copies visible; k-1 consumed

        const float2* wrow = (const float2*)((const char*)wcons0 +
                                             (size_t)slot * slotB);
#pragma unroll
        for (int i = 0; i < 4; i++) {
            float2 w = wrow[(size_t)i * 256];    // LDS.64, this thread's 2 cols
            const ulonglong2* sp =
                (const ulonglong2*)(shS + (size_t)(k * 4 + i) * KK);
            ulonglong2 p0 = sp[0], p1 = sp[1];   // warp-uniform LDS.128
            u64p sn0 = p0.x, sn1 = p0.y, sn2 = p1.x, sn3 = p1.y;
            ulonglong2 p2 = sp[2], p3 = sp[3];
            u64p sn4 = p2.x, sn5 = p2.y, sn6 = p3.x, sn7 = p3.y;

            u64p d0 = mul2(sm[0][0], sn0);
            u64p d1 = mul2(sm[1][0], sn0);
            d0 = fma2(sm[0][1], sn1, d0); d1 = fma2(sm[1][1], sn1, d1);
            d0 = fma2(sm[0][2], sn2, d0); d1 = fma2(sm[1][2], sn2, d1);
            d0 = fma2(sm[0][3], sn3, d0); d1 = fma2(sm[1][3], sn3, d1);
            d0 = fma2(sm[0][4], sn4, d0); d1 = fma2(sm[1][4], sn4, d1);
            d0 = fma2(sm[0][5], sn5, d0); d1 = fma2(sm[1][5], sn5, d1);
            d0 = fma2(sm[0][6], sn6, d0); d1 = fma2(sm[1][6], sn6, d1);
            d0 = fma2(sm[0][7], sn7, d0); d1 = fma2(sm[1][7], sn7, d1);

            acc0 = fma2(pk2(w.x, w.x), d0, acc0);
            acc1 = fma2(pk2(w.y, w.y), d1, acc1);
            den0 += w.x;
            den1 += w.y;
        }
        slot  = (slot  == 4) ? 0 : slot + 1;
        islot = (islot == 4) ? 0 : islot + 1;
    }

    float tnum = hsum2(acc0) + hsum2(acc1);
    float tden = den0 + den1;

    // Block reduction -> one double atomic per block
    __syncthreads();
    rn[tid] = tnum; rd[tid] = tden;
    __syncthreads();
#pragma unroll
    for (int s = 128; s > 0; s >>= 1) {
        if (tid < s) { rn[tid] += rn[tid + s]; rd[tid] += rd[tid + s]; }
        __syncthreads();
    }
    if (tid == 0) {
        atomicAdd(&g_num, (double)rn[0]);
        atomicAdd(&g_den, (double)rd[0]);
    }

    // Fused StS partial: the x==0 blocks cover every row of every batch
    // exactly once; shS is still resident.
    if (blockIdx.x == 0) {
        int k = tid >> 4, j = tid & 15;
        float a0 = 0.f, a1 = 0.f;
#pragma unroll 4
        for (int r = 0; r < 256; r += 2) {
            a0 = fmaf(shS[r * 16 + k],       shS[r * 16 + j],       a0);
            a1 = fmaf(shS[(r + 1) * 16 + k], shS[(r + 1) * 16 + j], a1);
        }
        atomicAdd(&g_StS[b * 256 + tid], (double)(a0 + a1));
    }

    // Fused finalize: last block to finish computes the loss.
    __threadfence();
    __syncthreads();
    __shared__ unsigned s_isLast;
    if (tid == 0)
        s_isLast = (atomicAdd(&g_done, 1u) == W_GRID_BLOCKS - 1) ? 1u : 0u;
    __syncthreads();
    if (s_isLast) {
        int k = tid >> 4, j = tid & 15;
        float s = 0.f;
#pragma unroll
        for (int bi = 0; bi < BB; bi++) {
            float v = (float)__ldcg(&g_StS[bi * 256 + tid]); // L2 (bypass L1)
            float diff = v - (k == j ? 1.0f : 0.0f);
            s += diff * diff;
        }
        rn[tid] = s;
        __syncthreads();
#pragma unroll
        for (int st = 128; st > 0; st >>= 1) {
            if (tid < st) rn[tid] += rn[tid + st];
            __syncthreads();
        }
        if (tid == 0) {
            float ortho = sqrtf(rn[0]) / (float)BB;
            double num = __ldcg(&g_num), den = __ldcg(&g_den);
            out[loss_idx] = -(float)(num / den) + ortho;
            atomicExch(&g_done, 0u);  // reset for next replay
        }
    }
}

// ---------------------------------------------------------------------------
// Launch
// ---------------------------------------------------------------------------
extern "C" void kernel_launch(void* const* d_in, const int* in_sizes, int n_in,
                              void* d_out, int out_size) {
    const float* W = nullptr;
    const float* logits = nullptr;
    for (int i = 0; i < n_in; i++) {
        long sz = (long)in_sizes[i];
        if (sz == (long)BB * NN * NN)      W      = (const float*)d_in[i];
        else if (sz == (long)BB * NN * KK) logits = (const float*)d_in[i];
        // features [B,N,D] is unused by the reference computation
    }
    float* out = (float*)d_out;

    bool want_S    = (out_size >= BNK);
    bool want_loss = (out_size == 1) || (out_size == BNK + 1);

    cudaFuncSetAttribute(w_pass_kernel,
                         cudaFuncAttributeMaxDynamicSharedMemorySize, DYN_SMEM);

    softmax_kernel<<<(BB * NN) / 256, 256>>>(logits, want_S ? out : nullptr);
    if (want_loss) {
        int loss_idx = (out_size == 1) ? 0 : BNK;
        w_pass_kernel<<<dim3(NN / 512, NN / 256, BB), 256, DYN_SMEM>>>(
            W, out, loss_idx);
    }
}

// round 15
// speedup vs baseline: 1.0667x; 1.0667x over previous
#include <cuda_runtime.h>
#include <math.h>
#include <stdint.h>

// Problem constants
#define BB 4
#define NN 8192
#define KK 16
#define BNK (BB * NN * KK)   // 524288

#define W_GRID_BLOCKS (16 * 32 * 4)  // w_pass grid (x*y*z) = 2048
// ring: 8 warps * 4 slots * 1KB = 32KB; shS 16KB; rn/rd 2KB
#define DYN_SMEM (32768 + 256*16*4 + 2*256*4)   // 51200

// ---------------------------------------------------------------------------
// Device scratch (no allocations allowed)
// ---------------------------------------------------------------------------
__device__ float    g_S[BNK];            // softmax(logits)
__device__ double   g_StS[BB * KK * KK]; // per-batch S^T S (1024 doubles)
__device__ double   g_num;               // sum W[n,m] * dot(S_n, S_m)
__device__ double   g_den;               // sum W
__device__ unsigned g_done;              // finished-block counter

// ---------------------------------------------------------------------------
// Packed f32x2 helpers
// ---------------------------------------------------------------------------
typedef unsigned long long u64p; // carrier for packed 2 x fp32

__device__ __forceinline__ u64p pk2(float lo, float hi) {
    u64p d;
    asm("mov.b64 %0, {%1, %2};" : "=l"(d) : "f"(lo), "f"(hi));
    return d;
}
__device__ __forceinline__ u64p mul2(u64p a, u64p b) {
    u64p d;
    asm("mul.rn.f32x2 %0, %1, %2;" : "=l"(d) : "l"(a), "l"(b));
    return d;
}
__device__ __forceinline__ u64p fma2(u64p a, u64p b, u64p c) {
    u64p d;
    asm("fma.rn.f32x2 %0, %1, %2, %3;" : "=l"(d) : "l"(a), "l"(b), "l"(c));
    return d;
}
__device__ __forceinline__ u64p add2(u64p a, u64p b) {
    u64p d;
    asm("add.rn.f32x2 %0, %1, %2;" : "=l"(d) : "l"(a), "l"(b));
    return d;
}
__device__ __forceinline__ float hsum2(u64p d) {
    float lo, hi;
    asm("mov.b64 {%0, %1}, %2;" : "=f"(lo), "=f"(hi) : "l"(d));
    return lo + hi;
}

// ---------------------------------------------------------------------------
// cp.async 16B L1-bypass (.cg). R13 lesson: 8B .ca made L1 the wall.
// ---------------------------------------------------------------------------
__device__ __forceinline__ void cp_async16(uint32_t smem_addr, const void* gptr) {
    asm volatile("cp.async.cg.shared.global [%0], [%1], 16;"
                 :: "r"(smem_addr), "l"(gptr) : "memory");
}
#define CP_COMMIT() asm volatile("cp.async.commit_group;" ::: "memory")
#define CP_WAIT3()  asm volatile("cp.async.wait_group 3;" ::: "memory")

// ---------------------------------------------------------------------------
// Softmax over K=16 per row. One thread per row. Block 0 zeroes ALL
// accumulators (strided — 1024 StS entries > 256 threads).
// ---------------------------------------------------------------------------
__global__ void softmax_kernel(const float* __restrict__ logits,
                               float* __restrict__ outS) {
    if (blockIdx.x == 0) {
        int t = threadIdx.x;
        for (int i = t; i < BB * KK * KK; i += 256) g_StS[i] = 0.0;
        if (t == 0) { g_num = 0.0; g_den = 0.0; }
    }
    int row = blockIdx.x * blockDim.x + threadIdx.x; // 0 .. B*N-1
    const float4* lp = (const float4*)(logits + (size_t)row * KK);
    float4 v0 = lp[0], v1 = lp[1], v2 = lp[2], v3 = lp[3];
    float v[16] = { v0.x, v0.y, v0.z, v0.w, v1.x, v1.y, v1.z, v1.w,
                    v2.x, v2.y, v2.z, v2.w, v3.x, v3.y, v3.z, v3.w };
    float mx = v[0];
#pragma unroll
    for (int i = 1; i < 16; i++) mx = fmaxf(mx, v[i]);
    float s = 0.f;
#pragma unroll
    for (int i = 0; i < 16; i++) { v[i] = expf(v[i] - mx); s += v[i]; }
    float inv = 1.0f / s;
    float4 o0 = make_float4(v[0]*inv,  v[1]*inv,  v[2]*inv,  v[3]*inv);
    float4 o1 = make_float4(v[4]*inv,  v[5]*inv,  v[6]*inv,  v[7]*inv);
    float4 o2 = make_float4(v[8]*inv,  v[9]*inv,  v[10]*inv, v[11]*inv);
    float4 o3 = make_float4(v[12]*inv, v[13]*inv, v[14]*inv, v[15]*inv);
    float4* sp = (float4*)(g_S + (size_t)row * KK);
    sp[0] = o0; sp[1] = o1; sp[2] = o2; sp[3] = o3;
    if (outS) {
        float4* op = (float4*)(outS + (size_t)row * KK);
        op[0] = o0; op[1] = o1; op[2] = o2; op[3] = o3;
    }
}

// ---------------------------------------------------------------------------
// Fused main pass:
//   num += W[b,n,m] * dot16(S_n, S_m);  den += W[b,n,m]
//   + StS partials (blockIdx.x==0 blocks) + finalize (last block).
//
// 256 threads = 8 warps, 3 CTAs/SM (24 warps). Each warp owns an independent
// 64-column strip and a PRIVATE 4-slot cp.async ring (1KB chunks = 4 rows).
// Producer == consumer warp: per chunk each lane issues 2x 16B cp.async.cg
// (16 lanes cover one 256B row, fully coalesced, L1-bypass), then
// CP_WAIT3 + __syncwarp() makes the chunk visible — NO block barriers
// (R14 lesson), 16B .cg copies (R13 lesson), 24 warps (R12 lesson).
// Each lane computes 2 columns (sm packed in 32 regs -> 76 regs total).
// Grid: (16 col strips, 32 row groups, B) = 2048 blocks.
// ---------------------------------------------------------------------------
__global__ void __launch_bounds__(256, 3)
w_pass_kernel(const float* __restrict__ W, float* __restrict__ out,
              int loss_idx) {
    extern __shared__ char dyn[];
    float* shW = (float*)dyn;                 // [8 warps][4 slots][4][64] 32KB
    float* shS = (float*)(dyn + 32768);       // 256 rows x 16 = 16KB
    float* rn  = shS + 256 * 16;              // 1KB
    float* rd  = rn + 256;                    // 1KB

    const int tid  = threadIdx.x;
    const int lane = tid & 31;
    const int warp = tid >> 5;
    const int b  = blockIdx.z;
    const int c0 = (blockIdx.x * 8 + warp) * 64 + lane * 2; // 2 columns m
    const int r0 = blockIdx.y * 256;                         // 256 rows

    // --- warp-private ring addressing ---
    // producer: lane covers rows {2*half, 2*half+1} of the chunk, 16B seg each
    const int half = lane >> 4;           // 0 or 1
    const int seg  = lane & 15;           // 16B segment within a 256B row
    const uint32_t wringB = (uint32_t)__cvta_generic_to_shared(shW)
                          + (uint32_t)warp * 4096;          // 4KB per warp
    const uint32_t po1 = (uint32_t)((half * 2) * 256 + seg * 16);
    const uint32_t po2 = po1 + 256;                          // next row
    // gmem: this warp's 64-col strip
    const float* gbase = W + ((size_t)b * NN + r0) * NN
                           + (size_t)(blockIdx.x * 8 + warp) * 64;
    const size_t go1 = (size_t)(half * 2) * NN + (size_t)seg * 4;
    const size_t go2 = go1 + NN;

    // Stage 256 S_n rows (16KB) once
    {
        const float4* src = (const float4*)(g_S + ((size_t)b * NN + r0) * KK);
        float4* dst = (float4*)shS;
        dst[tid]       = src[tid];
        dst[tid + 256] = src[tid + 256];
        dst[tid + 512] = src[tid + 512];
        dst[tid + 768] = src[tid + 768];
    }

    // Pre-pack S_m for this thread's 2 columns: 2 x 8 packed pairs (32 regs)
    u64p sm[2][8];
#pragma unroll
    for (int jj = 0; jj < 2; jj++) {
        const float4* sp = (const float4*)(g_S + ((size_t)b * NN + (c0 + jj)) * KK);
        float4 a = __ldg(sp), b4 = __ldg(sp + 1), c = __ldg(sp + 2), d = __ldg(sp + 3);
        sm[jj][0] = pk2(a.x, a.y);   sm[jj][1] = pk2(a.z, a.w);
        sm[jj][2] = pk2(b4.x, b4.y); sm[jj][3] = pk2(b4.z, b4.w);
        sm[jj][4] = pk2(c.x, c.y);   sm[jj][5] = pk2(c.z, c.w);
        sm[jj][6] = pk2(d.x, d.y);   sm[jj][7] = pk2(d.z, d.w);
    }
    __syncthreads();   // shS resident

    // Prologue: chunks 0,1,2 into slots 0,1,2 of this warp's ring
#pragma unroll
    for (int k = 0; k < 3; k++) {
        const float* p = gbase + (size_t)k * 4 * NN;
        const uint32_t sb = wringB + (uint32_t)k * 1024;
        cp_async16(sb + po1, p + go1);
        cp_async16(sb + po2, p + go2);
        CP_COMMIT();
    }

    u64p acc0 = 0, acc1 = 0;      // packed num accumulators (one per column)
    u64p denp = 0;                // packed den accumulator

    // consumer base: this lane's 8B (2 cols) in row 0 of slot 0
    const char* wcons = (const char*)shW + warp * 4096 + lane * 8;

#pragma unroll 1
    for (int k = 0; k < 64; k++) {               // 64 chunks x 4 rows
        const int slot = k & 3;
        if (k + 3 < 64) {
            const float* p = gbase + (size_t)(k + 3) * 4 * NN;
            const uint32_t sb = wringB + (uint32_t)((k + 3) & 3) * 1024;
            cp_async16(sb + po1, p + go1);
            cp_async16(sb + po2, p + go2);
        }
        CP_COMMIT();     // empty commits on tail keep group count exact
        CP_WAIT3();      // own copies of chunk k drained
        __syncwarp();    // whole warp's chunk-k copies visible (warp-private)

        const char* wrow = wcons + slot * 1024;
#pragma unroll
        for (int i = 0; i < 4; i++) {
            u64p w8 = *(const u64p*)(wrow + i * 256);   // LDS.64: (w0,w1) packed
            float w0, w1;
            asm("mov.b64 {%0, %1}, %2;" : "=f"(w0), "=f"(w1) : "l"(w8));
            const ulonglong2* sp =
                (const ulonglong2*)(shS + (size_t)(k * 4 + i) * KK);
            ulonglong2 p0 = sp[0], p1 = sp[1];   // warp-uniform LDS.128
            u64p sn0 = p0.x, sn1 = p0.y, sn2 = p1.x, sn3 = p1.y;
            ulonglong2 p2 = sp[2], p3 = sp[3];
            u64p sn4 = p2.x, sn5 = p2.y, sn6 = p3.x, sn7 = p3.y;

            u64p d0 = mul2(sm[0][0], sn0);
            u64p d1 = mul2(sm[1][0], sn0);
            d0 = fma2(sm[0][1], sn1, d0); d1 = fma2(sm[1][1], sn1, d1);
            d0 = fma2(sm[0][2], sn2, d0); d1 = fma2(sm[1][2], sn2, d1);
            d0 = fma2(sm[0][3], sn3, d0); d1 = fma2(sm[1][3], sn3, d1);
            d0 = fma2(sm[0][4], sn4, d0); d1 = fma2(sm[1][4], sn4, d1);
            d0 = fma2(sm[0][5], sn5, d0); d1 = fma2(sm[1][5], sn5, d1);
            d0 = fma2(sm[0][6], sn6, d0); d1 = fma2(sm[1][6], sn6, d1);
            d0 = fma2(sm[0][7], sn7, d0); d1 = fma2(sm[1][7], sn7, d1);

            acc0 = fma2(pk2(w0, w0), d0, acc0);
            acc1 = fma2(pk2(w1, w1), d1, acc1);
            denp = add2(denp, w8);               // packed den, zero extra movs
        }
    }

    float tnum = hsum2(acc0) + hsum2(acc1);
    float tden = hsum2(denp);

    // Block reduction -> one double atomic per block
    __syncthreads();
    rn[tid] = tnum; rd[tid] = tden;
    __syncthreads();
#pragma unroll
    for (int s = 128; s > 0; s >>= 1) {
        if (tid < s) { rn[tid] += rn[tid + s]; rd[tid] += rd[tid + s]; }
        __syncthreads();
    }
    if (tid == 0) {
        atomicAdd(&g_num, (double)rn[0]);
        atomicAdd(&g_den, (double)rd[0]);
    }

    // Fused StS partial: the x==0 blocks cover every row of every batch
    // exactly once; shS is still resident.
    if (blockIdx.x == 0) {
        int k = tid >> 4, j = tid & 15;
        float a0 = 0.f, a1 = 0.f;
#pragma unroll 4
        for (int r = 0; r < 256; r += 2) {
            a0 = fmaf(shS[r * 16 + k],       shS[r * 16 + j],       a0);
            a1 = fmaf(shS[(r + 1) * 16 + k], shS[(r + 1) * 16 + j], a1);
        }
        atomicAdd(&g_StS[b * 256 + tid], (double)(a0 + a1));
    }

    // Fused finalize: last block to finish computes the loss.
    __threadfence();
    __syncthreads();
    __shared__ unsigned s_isLast;
    if (tid == 0)
        s_isLast = (atomicAdd(&g_done, 1u) == W_GRID_BLOCKS - 1) ? 1u : 0u;
    __syncthreads();
    if (s_isLast) {
        int k = tid >> 4, j = tid & 15;
        float s = 0.f;
#pragma unroll
        for (int bi = 0; bi < BB; bi++) {
            float v = (float)__ldcg(&g_StS[bi * 256 + tid]); // L2 (bypass L1)
            float diff = v - (k == j ? 1.0f : 0.0f);
            s += diff * diff;
        }
        rn[tid] = s;
        __syncthreads();
#pragma unroll
        for (int st = 128; st > 0; st >>= 1) {
            if (tid < st) rn[tid] += rn[tid + st];
            __syncthreads();
        }
        if (tid == 0) {
            float ortho = sqrtf(rn[0]) / (float)BB;
            double num = __ldcg(&g_num), den = __ldcg(&g_den);
            out[loss_idx] = -(float)(num / den) + ortho;
            atomicExch(&g_done, 0u);  // reset for next replay
        }
    }
}

// ---------------------------------------------------------------------------
// Launch
// ---------------------------------------------------------------------------
extern "C" void kernel_launch(void* const* d_in, const int* in_sizes, int n_in,
                              void* d_out, int out_size) {
    const float* W = nullptr;
    const float* logits = nullptr;
    for (int i = 0; i < n_in; i++) {
        long sz = (long)in_sizes[i];
        if (sz == (long)BB * NN * NN)      W      = (const float*)d_in[i];
        else if (sz == (long)BB * NN * KK) logits = (const float*)d_in[i];
        // features [B,N,D] is unused by the reference computation
    }
    float* out = (float*)d_out;

    bool want_S    = (out_size >= BNK);
    bool want_loss = (out_size == 1) || (out_size == BNK + 1);

    cudaFuncSetAttribute(w_pass_kernel,
                         cudaFuncAttributeMaxDynamicSharedMemorySize, DYN_SMEM);

    softmax_kernel<<<(BB * NN) / 256, 256>>>(logits, want_S ? out : nullptr);
    if (want_loss) {
        int loss_idx = (out_size == 1) ? 0 : BNK;
        w_pass_kernel<<<dim3(NN / 512, NN / 256, BB), 256, DYN_SMEM>>>(
            W, out, loss_idx);
    }
}

// round 16
// speedup vs baseline: 1.0949x; 1.0264x over previous
#include <cuda_runtime.h>
#include <math.h>
#include <stdint.h>

// Problem constants
#define BB 4
#define NN 8192
#define KK 16
#define BNK (BB * NN * KK)   // 524288

#define W_GRID_BLOCKS (8 * 32 * 4)   // w_pass grid (x*y*z) = 1024
#define DYN_SMEM (4*4*256*16 + 256*16*4 + 2*256*4)  // 65536+16384+2048 = 83968

// ---------------------------------------------------------------------------
// Device scratch (no allocations allowed)
// ---------------------------------------------------------------------------
__device__ float    g_S[BNK];            // softmax(logits)
__device__ double   g_StS[BB * KK * KK]; // per-batch S^T S (1024 doubles)
__device__ double   g_num;               // sum W[n,m] * dot(S_n, S_m)
__device__ double   g_den;               // sum W
__device__ unsigned g_done;              // finished-block counter

// ---------------------------------------------------------------------------
// Packed f32x2 helpers
// ---------------------------------------------------------------------------
typedef unsigned long long u64p; // carrier for packed 2 x fp32

__device__ __forceinline__ u64p pk2(float lo, float hi) {
    u64p d;
    asm("mov.b64 %0, {%1, %2};" : "=l"(d) : "f"(lo), "f"(hi));
    return d;
}
__device__ __forceinline__ u64p mul2(u64p a, u64p b) {
    u64p d;
    asm("mul.rn.f32x2 %0, %1, %2;" : "=l"(d) : "l"(a), "l"(b));
    return d;
}
__device__ __forceinline__ u64p fma2(u64p a, u64p b, u64p c) {
    u64p d;
    asm("fma.rn.f32x2 %0, %1, %2, %3;" : "=l"(d) : "l"(a), "l"(b), "l"(c));
    return d;
}
__device__ __forceinline__ u64p add2(u64p a, u64p b) {
    u64p d;
    asm("add.rn.f32x2 %0, %1, %2;" : "=l"(d) : "l"(a), "l"(b));
    return d;
}
__device__ __forceinline__ float hsum2(u64p d) {
    float lo, hi;
    asm("mov.b64 {%0, %1}, %2;" : "=f"(lo), "=f"(hi) : "l"(d));
    return lo + hi;
}
// duplicate lo/hi half of a packed pair: (x,y) -> (x,x) / (y,y)
__device__ __forceinline__ u64p dup_lo(u64p p) {
    u64p d;
    asm("{ .reg .f32 l, h; mov.b64 {l, h}, %1; mov.b64 %0, {l, l}; }"
        : "=l"(d) : "l"(p));
    return d;
}
__device__ __forceinline__ u64p dup_hi(u64p p) {
    u64p d;
    asm("{ .reg .f32 l, h; mov.b64 {l, h}, %1; mov.b64 %0, {h, h}; }"
        : "=l"(d) : "l"(p));
    return d;
}

// ---------------------------------------------------------------------------
// cp.async 16B L1-bypass (.cg — R13 lesson) + L2 prefetch
// ---------------------------------------------------------------------------
__device__ __forceinline__ void cp_async16(uint32_t smem_addr, const void* gptr) {
    asm volatile("cp.async.cg.shared.global [%0], [%1], 16;"
                 :: "r"(smem_addr), "l"(gptr) : "memory");
}
__device__ __forceinline__ void prefetch_l2(const void* gptr) {
    asm volatile("prefetch.global.L2 [%0];" :: "l"(gptr));
}
#define CP_COMMIT() asm volatile("cp.async.commit_group;" ::: "memory")
#define CP_WAIT3()  asm volatile("cp.async.wait_group 3;" ::: "memory")

// ---------------------------------------------------------------------------
// Softmax over K=16 per row. One thread per row. Block 0 zeroes ALL
// accumulators (strided — 1024 StS entries > 256 threads).
// ---------------------------------------------------------------------------
__global__ void softmax_kernel(const float* __restrict__ logits,
                               float* __restrict__ outS) {
    if (blockIdx.x == 0) {
        int t = threadIdx.x;
        for (int i = t; i < BB * KK * KK; i += 256) g_StS[i] = 0.0;
        if (t == 0) { g_num = 0.0; g_den = 0.0; }
    }
    int row = blockIdx.x * blockDim.x + threadIdx.x; // 0 .. B*N-1
    const float4* lp = (const float4*)(logits + (size_t)row * KK);
    float4 v0 = lp[0], v1 = lp[1], v2 = lp[2], v3 = lp[3];
    float v[16] = { v0.x, v0.y, v0.z, v0.w, v1.x, v1.y, v1.z, v1.w,
                    v2.x, v2.y, v2.z, v2.w, v3.x, v3.y, v3.z, v3.w };
    float mx = v[0];
#pragma unroll
    for (int i = 1; i < 16; i++) mx = fmaxf(mx, v[i]);
    float s = 0.f;
#pragma unroll
    for (int i = 0; i < 16; i++) { v[i] = expf(v[i] - mx); s += v[i]; }
    float inv = 1.0f / s;
    float4 o0 = make_float4(v[0]*inv,  v[1]*inv,  v[2]*inv,  v[3]*inv);
    float4 o1 = make_float4(v[4]*inv,  v[5]*inv,  v[6]*inv,  v[7]*inv);
    float4 o2 = make_float4(v[8]*inv,  v[9]*inv,  v[10]*inv, v[11]*inv);
    float4 o3 = make_float4(v[12]*inv, v[13]*inv, v[14]*inv, v[15]*inv);
    float4* sp = (float4*)(g_S + (size_t)row * KK);
    sp[0] = o0; sp[1] = o1; sp[2] = o2; sp[3] = o3;
    if (outS) {
        float4* op = (float4*)(outS + (size_t)row * KK);
        op[0] = o0; op[1] = o1; op[2] = o2; op[3] = o3;
    }
}

// ---------------------------------------------------------------------------
// Fused main pass (R12 skeleton — best measured config):
//   num += W[b,n,m] * dot16(S_n, S_m);  den += W[b,n,m]
//   + StS partials (blockIdx.x==0 blocks) + finalize (last block).
//
// 256 threads = 8 warps, 2 CTAs/SM. Each thread owns 4 consecutive columns m
// (sm packed, 64 regs). 256 S_n rows staged once (16KB). W streams through a
// 4-slot cp.async.cg ring (16B/thread, per-thread wait_group, no barriers).
// NEW vs R12: (1) prefetch.global.L2 at distance 8 chunks (4 lanes per row
// cover the 4 cache lines) -> cp.async completes from L2 (~250cy) instead of
// DRAM (~600cy); (2) sn and w read as ulonglong2 (packed pairs, no MOVs);
// (3) den accumulated packed. ~18% fewer instructions per byte.
// Grid: (8 col strips, 32 row groups, B) = 1024 blocks.
// ---------------------------------------------------------------------------
__global__ void __launch_bounds__(256, 2)
w_pass_kernel(const float* __restrict__ W, float* __restrict__ out,
              int loss_idx) {
    extern __shared__ char dyn[];
    char*  shW = dyn;                                  // [4][4][256] 16B = 64KB
    float* shS = (float*)(dyn + 4 * 4 * 256 * 16);     // 256 rows x 16 = 16KB
    float* rn  = shS + 256 * 16;                       // 1KB
    float* rd  = rn + 256;                             // 1KB

    const int tid  = threadIdx.x;
    const int lane = tid & 31;
    const int warp = tid >> 5;
    const int b  = blockIdx.z;
    const int c0 = (blockIdx.x * 8 + warp) * 128 + lane * 4; // 4 columns m
    const int r0 = blockIdx.y * 256;                          // 256 rows

    const uint32_t swbase = (uint32_t)__cvta_generic_to_shared(shW)
                          + (uint32_t)tid * 16;
    const uint32_t plane  = 256 * 16;          // one row-in-chunk plane (4KB)
    const uint32_t slotsz = 4 * plane;         // one ring slot (16KB)

    // Stage 256 S_n rows (16KB) once
    {
        const float4* src = (const float4*)(g_S + ((size_t)b * NN + r0) * KK);
        float4* dst = (float4*)shS;
        dst[tid]       = src[tid];
        dst[tid + 256] = src[tid + 256];
        dst[tid + 512] = src[tid + 512];
        dst[tid + 768] = src[tid + 768];
    }

    // Pre-pack S_m for this thread's 4 columns: 4 x 8 packed pairs (64 regs)
    u64p sm[4][8];
#pragma unroll
    for (int jj = 0; jj < 4; jj++) {
        const ulonglong2* sp =
            (const ulonglong2*)(g_S + ((size_t)b * NN + (c0 + jj)) * KK);
        ulonglong2 q0 = __ldg(sp), q1 = __ldg(sp + 1),
                   q2 = __ldg(sp + 2), q3 = __ldg(sp + 3);
        sm[jj][0] = q0.x; sm[jj][1] = q0.y;
        sm[jj][2] = q1.x; sm[jj][3] = q1.y;
        sm[jj][4] = q2.x; sm[jj][5] = q2.y;
        sm[jj][6] = q3.x; sm[jj][7] = q3.y;
    }
    __syncthreads();   // shS tile resident

    const float* Wp = W + ((size_t)b * NN + r0) * NN + c0;
    // prefetch pointer: lanes 0,8,16,24 cover the warp's 4 cache lines per row
    const bool pf_lane = ((lane & 7) == 0);

    // Prologue: chunks 0,1,2 into slots 0,1,2; prefetch chunks 3..7 to L2
#pragma unroll
    for (int k = 0; k < 3; k++) {
        const float* p = Wp + (size_t)k * 4 * NN;
        const uint32_t sb = swbase + (uint32_t)k * slotsz;
#pragma unroll
        for (int i = 0; i < 4; i++)
            cp_async16(sb + (uint32_t)i * plane, p + (size_t)i * NN);
        CP_COMMIT();
    }
    if (pf_lane) {
#pragma unroll
        for (int k = 3; k < 8; k++)
#pragma unroll
            for (int i = 0; i < 4; i++)
                prefetch_l2(Wp + (size_t)(k * 4 + i) * NN);
    }

    u64p acc0 = 0, acc1 = 0, acc2 = 0, acc3 = 0; // packed num accumulators
    u64p den0 = 0, den1 = 0;                     // packed den accumulators

#pragma unroll 1
    for (int k = 0; k < 64; k++) {               // 64 chunks x 4 rows
        const int slot = k & 3;
        // prefetch chunk k+8 to L2 (dependency-free DRAM driver)
        if (pf_lane && k + 8 < 64) {
            const float* pp = Wp + (size_t)(k + 8) * 4 * NN;
            prefetch_l2(pp);
            prefetch_l2(pp + NN);
            prefetch_l2(pp + 2 * (size_t)NN);
            prefetch_l2(pp + 3 * (size_t)NN);
        }
        // Issue chunk k+3 (empty commit on tail keeps group count exact so
        // wait_group 3 always means "chunk k resident"). L2-hit completion.
        if (k + 3 < 64) {
            const float* p = Wp + (size_t)(k + 3) * 4 * NN;
            const uint32_t sb = swbase + (uint32_t)((k + 3) & 3) * slotsz;
#pragma unroll
            for (int i = 0; i < 4; i++)
                cp_async16(sb + (uint32_t)i * plane, p + (size_t)i * NN);
        }
        CP_COMMIT();
        CP_WAIT3();   // chunk k resident

        const char* wbase = shW + (size_t)slot * slotsz + (size_t)tid * 16;
#pragma unroll
        for (int i = 0; i < 4; i++) {
            ulonglong2 wv = *(const ulonglong2*)(wbase + (size_t)i * plane);
            u64p w01 = wv.x, w23 = wv.y;        // (w0,w1) (w2,w3) packed
            const ulonglong2* sp =
                (const ulonglong2*)(shS + (size_t)(k * 4 + i) * KK);
            ulonglong2 p0 = sp[0], p1 = sp[1];   // warp-uniform LDS.128
            u64p sn0 = p0.x, sn1 = p0.y, sn2 = p1.x, sn3 = p1.y;
            ulonglong2 p2 = sp[2], p3 = sp[3];
            u64p sn4 = p2.x, sn5 = p2.y, sn6 = p3.x, sn7 = p3.y;

            // 4 independent packed dot chains (ILP = 4)
            u64p d0 = mul2(sm[0][0], sn0);
            u64p d1 = mul2(sm[1][0], sn0);
            u64p d2 = mul2(sm[2][0], sn0);
            u64p d3 = mul2(sm[3][0], sn0);
            d0 = fma2(sm[0][1], sn1, d0); d1 = fma2(sm[1][1], sn1, d1);
            d2 = fma2(sm[2][1], sn1, d2); d3 = fma2(sm[3][1], sn1, d3);
            d0 = fma2(sm[0][2], sn2, d0); d1 = fma2(sm[1][2], sn2, d1);
            d2 = fma2(sm[2][2], sn2, d2); d3 = fma2(sm[3][2], sn2, d3);
            d0 = fma2(sm[0][3], sn3, d0); d1 = fma2(sm[1][3], sn3, d1);
            d2 = fma2(sm[2][3], sn3, d2); d3 = fma2(sm[3][3], sn3, d3);
            d0 = fma2(sm[0][4], sn4, d0); d1 = fma2(sm[1][4], sn4, d1);
            d2 = fma2(sm[2][4], sn4, d2); d3 = fma2(sm[3][4], sn4, d3);
            d0 = fma2(sm[0][5], sn5, d0); d1 = fma2(sm[1][5], sn5, d1);
            d2 = fma2(sm[2][5], sn5, d2); d3 = fma2(sm[3][5], sn5, d3);
            d0 = fma2(sm[0][6], sn6, d0); d1 = fma2(sm[1][6], sn6, d1);
            d2 = fma2(sm[2][6], sn6, d2); d3 = fma2(sm[3][6], sn6, d3);
            d0 = fma2(sm[0][7], sn7, d0); d1 = fma2(sm[1][7], sn7, d1);
            d2 = fma2(sm[2][7], sn7, d2); d3 = fma2(sm[3][7], sn7, d3);

            acc0 = fma2(dup_lo(w01), d0, acc0);
            acc1 = fma2(dup_hi(w01), d1, acc1);
            acc2 = fma2(dup_lo(w23), d2, acc2);
            acc3 = fma2(dup_hi(w23), d3, acc3);
            den0 = add2(den0, w01);
            den1 = add2(den1, w23);
        }
    }

    float tnum = (hsum2(acc0) + hsum2(acc1)) + (hsum2(acc2) + hsum2(acc3));
    float tden = hsum2(den0) + hsum2(den1);

    // Block reduction -> one double atomic per block
    __syncthreads();
    rn[tid] = tnum; rd[tid] = tden;
    __syncthreads();
#pragma unroll
    for (int s = 128; s > 0; s >>= 1) {
        if (tid < s) { rn[tid] += rn[tid + s]; rd[tid] += rd[tid + s]; }
        __syncthreads();
    }
    if (tid == 0) {
        atomicAdd(&g_num, (double)rn[0]);
        atomicAdd(&g_den, (double)rd[0]);
    }

    // Fused StS partial: the x==0 blocks cover every row of every batch
    // exactly once; shS is still resident.
    if (blockIdx.x == 0) {
        int k = tid >> 4, j = tid & 15;
        float a0 = 0.f, a1 = 0.f;
#pragma unroll 4
        for (int r = 0; r < 256; r += 2) {
            a0 = fmaf(shS[r * 16 + k],       shS[r * 16 + j],       a0);
            a1 = fmaf(shS[(r + 1) * 16 + k], shS[(r + 1) * 16 + j], a1);
        }
        atomicAdd(&g_StS[b * 256 + tid], (double)(a0 + a1));
    }

    // Fused finalize: last block to finish computes the loss.
    __threadfence();
    __syncthreads();
    __shared__ unsigned s_isLast;
    if (tid == 0)
        s_isLast = (atomicAdd(&g_done, 1u) == W_GRID_BLOCKS - 1) ? 1u : 0u;
    __syncthreads();
    if (s_isLast) {
        int k = tid >> 4, j = tid & 15;
        float s = 0.f;
#pragma unroll
        for (int bi = 0; bi < BB; bi++) {
            float v = (float)__ldcg(&g_StS[bi * 256 + tid]); // L2 (bypass L1)
            float diff = v - (k == j ? 1.0f : 0.0f);
            s += diff * diff;
        }
        rn[tid] = s;
        __syncthreads();
#pragma unroll
        for (int st = 128; st > 0; st >>= 1) {
            if (tid < st) rn[tid] += rn[tid + st];
            __syncthreads();
        }
        if (tid == 0) {
            float ortho = sqrtf(rn[0]) / (float)BB;
            double num = __ldcg(&g_num), den = __ldcg(&g_den);
            out[loss_idx] = -(float)(num / den) + ortho;
            atomicExch(&g_done, 0u);  // reset for next replay
        }
    }
}

// ---------------------------------------------------------------------------
// Launch
// ---------------------------------------------------------------------------
extern "C" void kernel_launch(void* const* d_in, const int* in_sizes, int n_in,
                              void* d_out, int out_size) {
    const float* W = nullptr;
    const float* logits = nullptr;
    for (int i = 0; i < n_in; i++) {
        long sz = (long)in_sizes[i];
        if (sz == (long)BB * NN * NN)      W      = (const float*)d_in[i];
        else if (sz == (long)BB * NN * KK) logits = (const float*)d_in[i];
        // features [B,N,D] is unused by the reference computation
    }
    float* out = (float*)d_out;

    bool want_S    = (out_size >= BNK);
    bool want_loss = (out_size == 1) || (out_size == BNK + 1);

    cudaFuncSetAttribute(w_pass_kernel,
                         cudaFuncAttributeMaxDynamicSharedMemorySize, DYN_SMEM);

    softmax_kernel<<<(BB * NN) / 256, 256>>>(logits, want_S ? out : nullptr);
    if (want_loss) {
        int loss_idx = (out_size == 1) ? 0 : BNK;
        w_pass_kernel<<<dim3(NN / 1024, NN / 256, BB), 256, DYN_SMEM>>>(
            W, out, loss_idx);
    }
}

// round 17
// speedup vs baseline: 1.1656x; 1.0645x over previous
#include <cuda_runtime.h>
#include <math.h>
#include <stdint.h>

// Problem constants
#define BB 4
#define NN 8192
#define KK 16
#define BNK (BB * NN * KK)   // 524288

#define STRIP   512          // m-columns per block (k-dim of the thin GEMM)
#define BROWS   256          // n-rows per block (8 warps x 32)
#define NCHUNK  64           // STRIP/8 : one m16n8k8 k-step per chunk
#define CH_STRIDE_F 12       // floats per padded chunk row (32B data + 16B pad)
#define CH_FLOATS (BROWS * CH_STRIDE_F)     // 3072 floats = 12KB per slot
#define RING_SLOTS 4
#define W_GRID_BLOCKS (16 * 32 * 4)  // (8192/512) x (8192/256) x B = 2048

// dyn smem: ring 48KB | Bfrag 32KB | shSn 16KB | rn 1KB | rd 1KB
#define OFF_BFRAG (RING_SLOTS * CH_FLOATS * 4)          // 49152
#define OFF_SHSN  (OFF_BFRAG + NCHUNK * 32 * 16)        // +32768 = 81920
#define OFF_RN    (OFF_SHSN + BROWS * KK * 4)           // +16384 = 98304
#define OFF_RD    (OFF_RN + 1024)
#define DYN_SMEM  (OFF_RD + 1024)                       // 100352

// ---------------------------------------------------------------------------
// Device scratch (no allocations allowed)
// ---------------------------------------------------------------------------
__device__ float    g_S[BNK];            // softmax(logits)
__device__ double   g_StS[BB * KK * KK]; // per-batch S^T S (1024 doubles)
__device__ double   g_num;               // sum W[n,m] * dot(S_n, S_m)
__device__ double   g_den;               // sum W
__device__ unsigned g_done;              // finished-block counter

// ---------------------------------------------------------------------------
// cp.async 16B L1-bypass (.cg)
// ---------------------------------------------------------------------------
__device__ __forceinline__ void cp_async16(uint32_t smem_addr, const void* gptr) {
    asm volatile("cp.async.cg.shared.global [%0], [%1], 16;"
                 :: "r"(smem_addr), "l"(gptr) : "memory");
}
#define CP_COMMIT() asm volatile("cp.async.commit_group;" ::: "memory")
#define CP_WAIT3()  asm volatile("cp.async.wait_group 3;" ::: "memory")

// ---------------------------------------------------------------------------
// mma.sync m16n8k8 tf32: D += A*B. A,B carry raw fp32 bits (HW uses tf32
// subset; truncation bias ~1e-4 on cut_loss, ~1e-7 on the ortho-dominated
// output — tolerance is 1e-3).
// ---------------------------------------------------------------------------
__device__ __forceinline__ void mma_tf32(
    float& d0, float& d1, float& d2, float& d3,
    uint32_t a0, uint32_t a1, uint32_t a2, uint32_t a3,
    uint32_t b0, uint32_t b1)
{
    asm volatile(
        "mma.sync.aligned.m16n8k8.row.col.f32.tf32.tf32.f32 "
        "{%0,%1,%2,%3}, {%4,%5,%6,%7}, {%8,%9}, {%0,%1,%2,%3};"
        : "+f"(d0), "+f"(d1), "+f"(d2), "+f"(d3)
        : "r"(a0), "r"(a1), "r"(a2), "r"(a3), "r"(b0), "r"(b1));
}

// ---------------------------------------------------------------------------
// Softmax over K=16 per row. One thread per row. Block 0 zeroes ALL
// accumulators (strided — 1024 StS entries > 256 threads).
// ---------------------------------------------------------------------------
__global__ void softmax_kernel(const float* __restrict__ logits,
                               float* __restrict__ outS) {
    if (blockIdx.x == 0) {
        int t = threadIdx.x;
        for (int i = t; i < BB * KK * KK; i += 256) g_StS[i] = 0.0;
        if (t == 0) { g_num = 0.0; g_den = 0.0; }
    }
    int row = blockIdx.x * blockDim.x + threadIdx.x; // 0 .. B*N-1
    const float4* lp = (const float4*)(logits + (size_t)row * KK);
    float4 v0 = lp[0], v1 = lp[1], v2 = lp[2], v3 = lp[3];
    float v[16] = { v0.x, v0.y, v0.z, v0.w, v1.x, v1.y, v1.z, v1.w,
                    v2.x, v2.y, v2.z, v2.w, v3.x, v3.y, v3.z, v3.w };
    float mx = v[0];
#pragma unroll
    for (int i = 1; i < 16; i++) mx = fmaxf(mx, v[i]);
    float s = 0.f;
#pragma unroll
    for (int i = 0; i < 16; i++) { v[i] = expf(v[i] - mx); s += v[i]; }
    float inv = 1.0f / s;
    float4 o0 = make_float4(v[0]*inv,  v[1]*inv,  v[2]*inv,  v[3]*inv);
    float4 o1 = make_float4(v[4]*inv,  v[5]*inv,  v[6]*inv,  v[7]*inv);
    float4 o2 = make_float4(v[8]*inv,  v[9]*inv,  v[10]*inv, v[11]*inv);
    float4 o3 = make_float4(v[12]*inv, v[13]*inv, v[14]*inv, v[15]*inv);
    float4* sp = (float4*)(g_S + (size_t)row * KK);
    sp[0] = o0; sp[1] = o1; sp[2] = o2; sp[3] = o3;
    if (outS) {
        float4* op = (float4*)(outS + (size_t)row * KK);
        op[0] = o0; op[1] = o1; op[2] = o2; op[3] = o3;
    }
}

// ---------------------------------------------------------------------------
// Tensor-core main pass (split-K, no T materialization):
//   T_partial[n,:] = sum_{m in strip} W[n,m] S[m,:]   (tf32 MMA, fp32 acc)
//   num_partial    = sum_n S[n,:]·T_partial[n,:]
//   den_partial    = sum W  (fp32, from raw A fragments)
//   + StS partials (x==0 blocks, from shSn) + finalize (last block).
//
// Block: 256 thr = 8 warps, 2 CTAs/SM. Warp owns 32 n-rows. W streams via the
// warp-private 4-slot cp.async.cg ring (R15 discipline: wait_group+syncwarp,
// no block barriers): chunk = 256 rows x 8 m (one k8 step), rows padded to
// 48B for conflict-free A-fragment LDS. S for the strip is pre-arranged in
// B-fragment order (one LDS.128 per step). Dot-product work moves to the
// tensor pipe: per 256 W elems/warp: 8 LDS.32 + 1 LDS.128 + 4 MMA + 8 FADD.
// Grid: (16 m-strips, 32 n-groups, B) = 2048 blocks.
// ---------------------------------------------------------------------------
__global__ void __launch_bounds__(256, 2)
w_pass_kernel(const float* __restrict__ W, float* __restrict__ out,
              int loss_idx) {
    extern __shared__ char dyn[];
    float* ring  = (float*)dyn;
    float* Bfrag = (float*)(dyn + OFF_BFRAG);  // [64 steps][32 lanes][4 words]
    float* shSn  = (float*)(dyn + OFF_SHSN);   // block's 256 n rows, fp32
    float* rn    = (float*)(dyn + OFF_RN);
    float* rd    = (float*)(dyn + OFF_RD);

    const int tid  = threadIdx.x;
    const int lane = tid & 31;
    const int warp = tid >> 5;
    const int b  = blockIdx.z;
    const int m0 = blockIdx.x * STRIP;        // strip start (k-dim)
    const int n0 = blockIdx.y * BROWS;        // block rows

    const int g = lane >> 2;                  // groupID
    const int t = lane & 3;                   // threadID_in_group

    // ---- stage shSn: block's 256 S rows (fp32, also used by StS/final dot)
    {
        const float4* src = (const float4*)(g_S + ((size_t)b * NN + n0) * KK);
        float4* dst = (float4*)shSn;
        dst[tid]       = src[tid];
        dst[tid + 256] = src[tid + 256];
        dst[tid + 512] = src[tid + 512];
        dst[tid + 768] = src[tid + 768];
    }

    // ---- stage Bfrag: strip's 512 S rows rearranged into m16n8k8 B-fragment
    // order. Value S[mloc, c] -> step s=mloc>>3, lane ((c&7)<<2)|(mloc&3),
    // word (mloc>>2 & 1) + 2*(c>>3).
    for (int idx = tid; idx < 2048; idx += 256) {
        int mloc = idx >> 2;
        int c4   = (idx & 3) * 4;
        float4 v = *(const float4*)(g_S + ((size_t)b * NN + m0 + mloc) * KK + c4);
        int s  = mloc >> 3;
        int tt = mloc & 3;
        int bs = (mloc >> 2) & 1;
        float vv[4] = { v.x, v.y, v.z, v.w };
#pragma unroll
        for (int i = 0; i < 4; i++) {
            int c = c4 + i;
            int ln = ((c & 7) << 2) | tt;
            Bfrag[((s * 32 + ln) << 2) + bs + 2 * (c >> 3)] = vv[i];
        }
    }
    __syncthreads();

    // ---- warp-private cp.async ring addressing ----
    // copy task: lane l covers rows 32w + j*16 + (l>>1), seg (l&1) of 32B row
    const int crow = 32 * warp + (lane >> 1);
    const int cseg = lane & 1;
    const float* Wrow = W + ((size_t)b * NN + n0 + crow) * NN + m0 + cseg * 4;
    const uint32_t ringU = (uint32_t)__cvta_generic_to_shared(ring);
    const uint32_t cpo   = (uint32_t)(crow * 48 + cseg * 16);

    // Prologue: chunks 0,1,2 into slots 0,1,2
#pragma unroll
    for (int k = 0; k < 3; k++) {
        const float* p = Wrow + k * 8;
        const uint32_t sb = ringU + (uint32_t)k * (CH_FLOATS * 4) + cpo;
        cp_async16(sb, p);
        cp_async16(sb + 16 * 48, p + 16 * (size_t)NN);
        CP_COMMIT();
    }

    // MMA accumulators: 2 row-groups (rows 32w+{0..15}, {16..31}) x 2 N-halves
    float a00=0,a01=0,a02=0,a03=0;   // rows g,g+8   clusters 0-7
    float a10=0,a11=0,a12=0,a13=0;   // rows g,g+8   clusters 8-15
    float a20=0,a21=0,a22=0,a23=0;   // rows +16     clusters 0-7
    float a30=0,a31=0,a32=0,a33=0;   // rows +16     clusters 8-15
    float den0=0.f, den1=0.f, den2=0.f, den3=0.f;

    const int r0 = 32 * warp + g;    // A-frag row base (local)

#pragma unroll 1
    for (int k = 0; k < NCHUNK; k++) {
        if (k + 3 < NCHUNK) {
            const float* p = Wrow + (k + 3) * 8;
            const uint32_t sb = ringU + (uint32_t)((k + 3) & 3) * (CH_FLOATS * 4) + cpo;
            cp_async16(sb, p);
            cp_async16(sb + 16 * 48, p + 16 * (size_t)NN);
        }
        CP_COMMIT();     // empty commits on tail keep group count exact
        CP_WAIT3();      // own chunk-k copies drained
        __syncwarp();    // all lanes of this warp have passed their waits

        const float* As = ring + (size_t)(k & 3) * CH_FLOATS;
        // B fragment: one LDS.128
        float4 bfv = *(const float4*)(Bfrag + ((size_t)(k * 32 + lane) << 2));
        uint32_t b0 = __float_as_uint(bfv.x), b1 = __float_as_uint(bfv.y);
        uint32_t b2 = __float_as_uint(bfv.z), b3 = __float_as_uint(bfv.w);

        // A fragments, row-group 0 (conflict-free: 48B row stride)
        float f0 = As[(r0)      * CH_STRIDE_F + t];
        float f1 = As[(r0 + 8)  * CH_STRIDE_F + t];
        float f2 = As[(r0)      * CH_STRIDE_F + t + 4];
        float f3 = As[(r0 + 8)  * CH_STRIDE_F + t + 4];
        uint32_t u0 = __float_as_uint(f0), u1 = __float_as_uint(f1);
        uint32_t u2 = __float_as_uint(f2), u3 = __float_as_uint(f3);
        mma_tf32(a00, a01, a02, a03, u0, u1, u2, u3, b0, b1);
        mma_tf32(a10, a11, a12, a13, u0, u1, u2, u3, b2, b3);
        den0 += f0 + f1;
        den1 += f2 + f3;

        // A fragments, row-group 1 (rows +16)
        float f4 = As[(r0 + 16) * CH_STRIDE_F + t];
        float f5 = As[(r0 + 24) * CH_STRIDE_F + t];
        float f6 = As[(r0 + 16) * CH_STRIDE_F + t + 4];
        float f7 = As[(r0 + 24) * CH_STRIDE_F + t + 4];
        uint32_t u4 = __float_as_uint(f4), u5 = __float_as_uint(f5);
        uint32_t u6 = __float_as_uint(f6), u7 = __float_as_uint(f7);
        mma_tf32(a20, a21, a22, a23, u4, u5, u6, u7, b0, b1);
        mma_tf32(a30, a31, a32, a33, u4, u5, u6, u7, b2, b3);
        den2 += f4 + f5;
        den3 += f6 + f7;
    }

    // num_partial = sum_n S[n,:]·T_partial[n,:] from the accumulator layout:
    // c0/c1: row g,   cols 2t,2t+1 ; c2/c3: row g+8 (per 16-row group;
    // second MMA covers cluster cols +8).
    float tnum;
    {
        const float* Sn = shSn;
        int ra = r0, rb = r0 + 8, rc = r0 + 16, rd_ = r0 + 24;
        int ca = 2 * t, cb = 2 * t + 8;
        tnum =
            Sn[ra * 16 + ca] * a00 + Sn[ra * 16 + ca + 1] * a01 +
            Sn[rb * 16 + ca] * a02 + Sn[rb * 16 + ca + 1] * a03 +
            Sn[ra * 16 + cb] * a10 + Sn[ra * 16 + cb + 1] * a11 +
            Sn[rb * 16 + cb] * a12 + Sn[rb * 16 + cb + 1] * a13 +
            Sn[rc * 16 + ca] * a20 + Sn[rc * 16 + ca + 1] * a21 +
            Sn[rd_ * 16 + ca] * a22 + Sn[rd_ * 16 + ca + 1] * a23 +
            Sn[rc * 16 + cb] * a30 + Sn[rc * 16 + cb + 1] * a31 +
            Sn[rd_ * 16 + cb] * a32 + Sn[rd_ * 16 + cb + 1] * a33;
    }
    float tden = (den0 + den1) + (den2 + den3);

    // Block reduction -> one double atomic per block
    __syncthreads();
    rn[tid] = tnum; rd[tid] = tden;
    __syncthreads();
#pragma unroll
    for (int s = 128; s > 0; s >>= 1) {
        if (tid < s) { rn[tid] += rn[tid + s]; rd[tid] += rd[tid + s]; }
        __syncthreads();
    }
    if (tid == 0) {
        atomicAdd(&g_num, (double)rn[0]);
        atomicAdd(&g_den, (double)rd[0]);
    }

    // Fused StS partial (fp32-exact): x==0 blocks cover every row once.
    if (blockIdx.x == 0) {
        int k = tid >> 4, j = tid & 15;
        float p0 = 0.f, p1 = 0.f;
#pragma unroll 4
        for (int r = 0; r < BROWS; r += 2) {
            p0 = fmaf(shSn[r * 16 + k],       shSn[r * 16 + j],       p0);
            p1 = fmaf(shSn[(r + 1) * 16 + k], shSn[(r + 1) * 16 + j], p1);
        }
        atomicAdd(&g_StS[b * 256 + tid], (double)(p0 + p1));
    }

    // Fused finalize: last block computes the loss.
    __threadfence();
    __syncthreads();
    __shared__ unsigned s_isLast;
    if (tid == 0)
        s_isLast = (atomicAdd(&g_done, 1u) == W_GRID_BLOCKS - 1) ? 1u : 0u;
    __syncthreads();
    if (s_isLast) {
        int k = tid >> 4, j = tid & 15;
        float s = 0.f;
#pragma unroll
        for (int bi = 0; bi < BB; bi++) {
            float v = (float)__ldcg(&g_StS[bi * 256 + tid]); // L2 (bypass L1)
            float diff = v - (k == j ? 1.0f : 0.0f);
            s += diff * diff;
        }
        rn[tid] = s;
        __syncthreads();
#pragma unroll
        for (int st = 128; st > 0; st >>= 1) {
            if (tid < st) rn[tid] += rn[tid + st];
            __syncthreads();
        }
        if (tid == 0) {
            float ortho = sqrtf(rn[0]) / (float)BB;
            double num = __ldcg(&g_num), den = __ldcg(&g_den);
            out[loss_idx] = -(float)(num / den) + ortho;
            atomicExch(&g_done, 0u);  // reset for next replay
        }
    }
}

// ---------------------------------------------------------------------------
// Launch
// ---------------------------------------------------------------------------
extern "C" void kernel_launch(void* const* d_in, const int* in_sizes, int n_in,
                              void* d_out, int out_size) {
    const float* W = nullptr;
    const float* logits = nullptr;
    for (int i = 0; i < n_in; i++) {
        long sz = (long)in_sizes[i];
        if (sz == (long)BB * NN * NN)      W      = (const float*)d_in[i];
        else if (sz == (long)BB * NN * KK) logits = (const float*)d_in[i];
        // features [B,N,D] is unused by the reference computation
    }
    float* out = (float*)d_out;

    bool want_S    = (out_size >= BNK);
    bool want_loss = (out_size == 1) || (out_size == BNK + 1);

    cudaFuncSetAttribute(w_pass_kernel,
                         cudaFuncAttributeMaxDynamicSharedMemorySize, DYN_SMEM);

    softmax_kernel<<<(BB * NN) / 256, 256>>>(logits, want_S ? out : nullptr);
    if (want_loss) {
        int loss_idx = (out_size == 1) ? 0 : BNK;
        w_pass_kernel<<<dim3(NN / STRIP, NN / BROWS, BB), 256, DYN_SMEM>>>(
            W, out, loss_idx);
    }
}